// round 7
// baseline (speedup 1.0000x reference)
#include <cuda_runtime.h>

// ============================================================================
// FrFDConv: weights = polar(FrFT2D(spec)) . polar_w  ;  out = conv3x3(x, weights)
// R4: fp32 direct conv with packed fma.rn.f32x2.
//   - weights pre-duplicated as {w,w} 64-bit pairs at generation time
//     (removes 144 ALU MOVs per ci-iteration -> alu pipe ~45% -> <10%)
//   - staging offsets hoisted out of the ci loop (no more idx/34 per ci)
//   - double-buffered input patch, register prefetch, 1 barrier per ci
// ============================================================================

#define PI_F 3.14159265358979323846f

typedef unsigned long long ull;

// Duplicated-pair weights: g_w2[(co*64+ci)*9 + t] = {w, w}
__device__ ull g_w2[64 * 64 * 9];

// ------------------------------ complex helpers -----------------------------
struct c2f { float re, im; };

__device__ __forceinline__ c2f cmul(c2f a, c2f b) {
    return { a.re * b.re - a.im * b.im, a.re * b.im + a.im * b.re };
}
__device__ __forceinline__ c2f cadd(c2f a, c2f b) { return { a.re + b.re, a.im + b.im }; }
__device__ __forceinline__ c2f cscale(c2f a, float s) { return { a.re * s, a.im * s }; }
__device__ __forceinline__ c2f cis(float th) {
    float s, c;
    sincosf(th, &s, &c);
    return { c, s };
}

// 1-D FrFT for N=3, fully unrolled (validated in R4's passing kernel).
__device__ __forceinline__ void frft3(c2f& v0, c2f& v1, c2f& v2,
                                      c2f c1a, c2f c1b, c2f c2a, c2f c2b,
                                      float scl) {
    const c2f w  = { -0.5f, -0.8660254037844386f };
    const c2f wb = { -0.5f,  0.8660254037844386f };

    c2f u0 = cmul(v1, c1a);
    c2f u1 = cmul(v2, c1b);
    c2f u2 = v0;

    c2f F0 = cadd(cadd(u0, u1), u2);
    c2f F1 = cadd(cadd(u0, cmul(u1, w )), cmul(u2, wb));
    c2f F2 = cadd(cadd(u0, cmul(u1, wb)), cmul(u2, w ));

    c2f G0 = cmul(F0, c2a);
    c2f G1 = cmul(F1, c2b);
    c2f G2 = F2;

    c2f y0 = cadd(cadd(G0, G1), G2);
    c2f y1 = cadd(cadd(G0, cmul(G1, wb)), cmul(G2, w ));
    c2f y2 = cadd(cadd(G0, cmul(G1, w )), cmul(G2, wb));

    float t3 = scl * (1.0f / 3.0f);
    c2f z0 = cscale(cmul(y0, c1a), t3);
    c2f z1 = cscale(cmul(y1, c1b), t3);
    c2f z2 = cscale(y2, t3);

    v0 = z2; v1 = z0; v2 = z1;
}

// ----------------------------- weight generation ----------------------------
__global__ void frfd_wgen_kernel(const float* __restrict__ spec,
                                 const float* __restrict__ alphap,
                                 const float* __restrict__ polarw) {
    int id = blockIdx.x * blockDim.x + threadIdx.x;
    if (id >= 64 * 64) return;

    float a = alphap[0];
    a = fminf(fmaxf(a, 1e-4f), 2.0f - 1e-4f);

    float t  = tanf(a * PI_F * 0.25f);
    float sa = sinf(a * PI_F * 0.5f);
    float scl = rsqrtf(fabsf(sa) + 1e-12f);

    c2f c1a = cis(-PI_F * 4.0f * t * (1.0f / 3.0f));
    c2f c1b = cis(-PI_F * t * (1.0f / 3.0f));
    float inv3sa = 1.0f / (3.0f * sa);
    c2f c2a = cis(-PI_F * 4.0f * inv3sa);
    c2f c2b = cis(-PI_F * inv3sa);

    c2f Z[3][3];
    const float* sp = spec + (size_t)id * 9;
#pragma unroll
    for (int i = 0; i < 3; i++)
#pragma unroll
        for (int j = 0; j < 3; j++)
            Z[i][j] = { sp[i * 3 + j], 0.0f };

#pragma unroll
    for (int i = 0; i < 3; i++)
        frft3(Z[i][0], Z[i][1], Z[i][2], c1a, c1b, c2a, c2b, scl);
#pragma unroll
    for (int j = 0; j < 3; j++)
        frft3(Z[0][j], Z[1][j], Z[2][j], c1a, c1b, c2a, c2b, scl);

    float pw0 = polarw[0];
    float pw1 = polarw[1];
    ull* gw = g_w2 + (size_t)id * 9;
#pragma unroll
    for (int i = 0; i < 3; i++)
#pragma unroll
        for (int j = 0; j < 3; j++) {
            float re = Z[i][j].re, im = Z[i][j].im;
            float mag = sqrtf(re * re + im * im);
            float ang = atan2f(im, re);
            float k = pw0 * mag + pw1 * (ang * (1.0f / PI_F));
            ull d;
            asm("mov.b64 %0, {%1, %1};" : "=l"(d) : "f"(k));
            gw[i * 3 + j] = d;
        }
}

// --------------------------------- conv3x3 ----------------------------------
// N=16, C=64 -> CO=64, H=W=224, pad 1.
// Block (16,8)=128 threads; tile 32x32 spatial x 8 co.
// Thread: 2 cols (f32x2) x 4 rows x 8 co = 32 packed accumulators.
// grid = (7, 7, 16*8); blockIdx.z = n*8 + cog.

__device__ __forceinline__ void fma2(ull& d, ull a, ull b) {
    asm("fma.rn.f32x2 %0, %1, %2, %0;" : "+l"(d) : "l"(a), "l"(b));
}

__global__ __launch_bounds__(128, 4)
void frfd_conv3x3_kernel(const float* __restrict__ x, float* __restrict__ out) {
    __shared__ __align__(16) float sPatch[2][34 * 34 + 2];   // double buffer
    __shared__ __align__(16) ull   sW[8 * 64 * 9];           // duplicated pairs

    const int tx  = threadIdx.x;       // 0..15 -> column pair
    const int ty  = threadIdx.y;       // 0..7  -> 4-row group
    const int tid = ty * 16 + tx;
    const int bz  = blockIdx.z;
    const int n   = bz >> 3;
    const int cog = bz & 7;

    // stage this block's duplicated weights (36 KB), 16B chunks
    {
        const ulonglong2* src =
            reinterpret_cast<const ulonglong2*>(g_w2 + (size_t)cog * (8 * 64 * 9));
        ulonglong2* dst = reinterpret_cast<ulonglong2*>(sW);
#pragma unroll 3
        for (int i = tid; i < (8 * 64 * 9) / 2; i += 128) dst[i] = src[i];
    }

    const int hb = blockIdx.y * 32;
    const int wb = blockIdx.x * 32;

    // -------- hoisted staging offsets: identical for every ci --------
    int goff[10];
#pragma unroll
    for (int k = 0; k < 10; ++k) {
        int idx = tid + k * 128;
        int pr  = idx / 34;
        int pc  = idx - pr * 34;
        int gh  = hb - 1 + pr;
        int gw2 = wb - 1 + pc;
        bool ok = (idx < 1156) && ((unsigned)gh < 224u) && ((unsigned)gw2 < 224u);
        goff[k] = ok ? gh * 224 + gw2 : -1;
    }

    const float* xn = x + (size_t)n * 64 * 224 * 224;

    // -------- prologue: stage ci = 0 into buffer 0 --------
    float v[10];
    {
        const float* xc = xn;
#pragma unroll
        for (int k = 0; k < 10; ++k)
            v[k] = (goff[k] >= 0) ? xc[goff[k]] : 0.0f;
#pragma unroll
        for (int k = 0; k < 9; ++k) sPatch[0][tid + k * 128] = v[k];
        if (tid < 4) sPatch[0][tid + 1152] = v[9];
    }
    __syncthreads();   // also orders the sW staging

    ull acc[8][4];
#pragma unroll
    for (int co = 0; co < 8; ++co)
#pragma unroll
        for (int rr = 0; rr < 4; ++rr) acc[co][rr] = 0ULL;

    for (int ci = 0; ci < 64; ++ci) {
        const int cur = ci & 1;

        // ---- prefetch ci+1 into registers (overlaps with compute) ----
        if (ci < 63) {
            const float* xc = xn + (size_t)(ci + 1) * (224 * 224);
#pragma unroll
            for (int k = 0; k < 10; ++k)
                v[k] = (goff[k] >= 0) ? xc[goff[k]] : 0.0f;
        }

        // ---- thread window: 6 rows of packed column pairs ----
        ull A[6], B[6], P[6];
#pragma unroll
        for (int r = 0; r < 6; ++r) {
            const float* rowp = &sPatch[cur][(4 * ty + r) * 34 + 2 * tx];
            A[r] = *reinterpret_cast<const ull*>(rowp);
            B[r] = *reinterpret_cast<const ull*>(rowp + 2);
            P[r] = (A[r] >> 32) | (B[r] << 32);
        }

        // ---- 8 co x 4 rows x 9 taps, weights via LDS.64 broadcast ----
        const ull* wci = sW + ci * 9;
#pragma unroll
        for (int co = 0; co < 8; ++co) {
            const ull* wp = wci + co * (64 * 9);
#pragma unroll
            for (int kh = 0; kh < 3; ++kh) {
                ull w0 = wp[kh * 3 + 0];
                ull w1 = wp[kh * 3 + 1];
                ull w2 = wp[kh * 3 + 2];
#pragma unroll
                for (int rr = 0; rr < 4; ++rr) {
                    fma2(acc[co][rr], A[rr + kh], w0);
                    fma2(acc[co][rr], P[rr + kh], w1);
                    fma2(acc[co][rr], B[rr + kh], w2);
                }
            }
        }

        // ---- store prefetched patch into the other buffer ----
        if (ci < 63) {
            float* dstp = sPatch[cur ^ 1];
#pragma unroll
            for (int k = 0; k < 9; ++k) dstp[tid + k * 128] = v[k];
            if (tid < 4) dstp[tid + 1152] = v[9];
        }
        __syncthreads();   // one barrier per ci
    }

    // ---- store: packed pair = contiguous (w, w+1) floats ----
#pragma unroll
    for (int co = 0; co < 8; ++co) {
        size_t cbase = ((size_t)n * 64 + (size_t)cog * 8 + co) * (224 * 224);
#pragma unroll
        for (int rr = 0; rr < 4; ++rr) {
            int h = hb + 4 * ty + rr;
            int w = wb + 2 * tx;
            *reinterpret_cast<ull*>(&out[cbase + (size_t)h * 224 + w]) = acc[co][rr];
        }
    }
}

// --------------------------------- launcher ---------------------------------
extern "C" void kernel_launch(void* const* d_in, const int* in_sizes, int n_in,
                              void* d_out, int out_size) {
    int ix = 0, ispec = 1, ialpha = 2, ipw = 3;
    for (int i = 0; i < n_in; ++i) {
        int s = in_sizes[i];
        if (s == 16 * 64 * 224 * 224) ix = i;
        else if (s == 64 * 64 * 3 * 3) ispec = i;
        else if (s == 1) ialpha = i;
        else if (s == 2) ipw = i;
    }
    const float* x     = (const float*)d_in[ix];
    const float* spec  = (const float*)d_in[ispec];
    const float* alpha = (const float*)d_in[ialpha];
    const float* pw    = (const float*)d_in[ipw];
    float* out = (float*)d_out;

    frfd_wgen_kernel<<<16, 256>>>(spec, alpha, pw);

    dim3 grid(7, 7, 16 * 8);
    dim3 block(16, 8);
    frfd_conv3x3_kernel<<<grid, block>>>(x, out);
}

// round 8
// speedup vs baseline: 1.0005x; 1.0005x over previous
#include <cuda_runtime.h>

// ============================================================================
// FrFDConv: weights = polar(FrFT2D(spec)) . polar_w  ;  out = conv3x3(x, weights)
// R4: fp32 direct conv with packed fma.rn.f32x2.
//   - weights pre-duplicated as {w,w} 64-bit pairs at generation time
//     (removes 144 ALU MOVs per ci-iteration -> alu pipe ~45% -> <10%)
//   - staging offsets hoisted out of the ci loop (no more idx/34 per ci)
//   - double-buffered input patch, register prefetch, 1 barrier per ci
// ============================================================================

#define PI_F 3.14159265358979323846f

typedef unsigned long long ull;

// Duplicated-pair weights: g_w2[(co*64+ci)*9 + t] = {w, w}
__device__ ull g_w2[64 * 64 * 9];

// ------------------------------ complex helpers -----------------------------
struct c2f { float re, im; };

__device__ __forceinline__ c2f cmul(c2f a, c2f b) {
    return { a.re * b.re - a.im * b.im, a.re * b.im + a.im * b.re };
}
__device__ __forceinline__ c2f cadd(c2f a, c2f b) { return { a.re + b.re, a.im + b.im }; }
__device__ __forceinline__ c2f cscale(c2f a, float s) { return { a.re * s, a.im * s }; }
__device__ __forceinline__ c2f cis(float th) {
    float s, c;
    sincosf(th, &s, &c);
    return { c, s };
}

// 1-D FrFT for N=3, fully unrolled (validated in R4's passing kernel).
__device__ __forceinline__ void frft3(c2f& v0, c2f& v1, c2f& v2,
                                      c2f c1a, c2f c1b, c2f c2a, c2f c2b,
                                      float scl) {
    const c2f w  = { -0.5f, -0.8660254037844386f };
    const c2f wb = { -0.5f,  0.8660254037844386f };

    c2f u0 = cmul(v1, c1a);
    c2f u1 = cmul(v2, c1b);
    c2f u2 = v0;

    c2f F0 = cadd(cadd(u0, u1), u2);
    c2f F1 = cadd(cadd(u0, cmul(u1, w )), cmul(u2, wb));
    c2f F2 = cadd(cadd(u0, cmul(u1, wb)), cmul(u2, w ));

    c2f G0 = cmul(F0, c2a);
    c2f G1 = cmul(F1, c2b);
    c2f G2 = F2;

    c2f y0 = cadd(cadd(G0, G1), G2);
    c2f y1 = cadd(cadd(G0, cmul(G1, wb)), cmul(G2, w ));
    c2f y2 = cadd(cadd(G0, cmul(G1, w )), cmul(G2, wb));

    float t3 = scl * (1.0f / 3.0f);
    c2f z0 = cscale(cmul(y0, c1a), t3);
    c2f z1 = cscale(cmul(y1, c1b), t3);
    c2f z2 = cscale(y2, t3);

    v0 = z2; v1 = z0; v2 = z1;
}

// ----------------------------- weight generation ----------------------------
__global__ void frfd_wgen_kernel(const float* __restrict__ spec,
                                 const float* __restrict__ alphap,
                                 const float* __restrict__ polarw) {
    int id = blockIdx.x * blockDim.x + threadIdx.x;
    if (id >= 64 * 64) return;

    float a = alphap[0];
    a = fminf(fmaxf(a, 1e-4f), 2.0f - 1e-4f);

    float t  = tanf(a * PI_F * 0.25f);
    float sa = sinf(a * PI_F * 0.5f);
    float scl = rsqrtf(fabsf(sa) + 1e-12f);

    c2f c1a = cis(-PI_F * 4.0f * t * (1.0f / 3.0f));
    c2f c1b = cis(-PI_F * t * (1.0f / 3.0f));
    float inv3sa = 1.0f / (3.0f * sa);
    c2f c2a = cis(-PI_F * 4.0f * inv3sa);
    c2f c2b = cis(-PI_F * inv3sa);

    c2f Z[3][3];
    const float* sp = spec + (size_t)id * 9;
#pragma unroll
    for (int i = 0; i < 3; i++)
#pragma unroll
        for (int j = 0; j < 3; j++)
            Z[i][j] = { sp[i * 3 + j], 0.0f };

#pragma unroll
    for (int i = 0; i < 3; i++)
        frft3(Z[i][0], Z[i][1], Z[i][2], c1a, c1b, c2a, c2b, scl);
#pragma unroll
    for (int j = 0; j < 3; j++)
        frft3(Z[0][j], Z[1][j], Z[2][j], c1a, c1b, c2a, c2b, scl);

    float pw0 = polarw[0];
    float pw1 = polarw[1];
    ull* gw = g_w2 + (size_t)id * 9;
#pragma unroll
    for (int i = 0; i < 3; i++)
#pragma unroll
        for (int j = 0; j < 3; j++) {
            float re = Z[i][j].re, im = Z[i][j].im;
            float mag = sqrtf(re * re + im * im);
            float ang = atan2f(im, re);
            float k = pw0 * mag + pw1 * (ang * (1.0f / PI_F));
            ull d;
            asm("mov.b64 %0, {%1, %1};" : "=l"(d) : "f"(k));
            gw[i * 3 + j] = d;
        }
}

// --------------------------------- conv3x3 ----------------------------------
// N=16, C=64 -> CO=64, H=W=224, pad 1.
// Block (16,8)=128 threads; tile 32x32 spatial x 8 co.
// Thread: 2 cols (f32x2) x 4 rows x 8 co = 32 packed accumulators.
// grid = (7, 7, 16*8); blockIdx.z = n*8 + cog.

__device__ __forceinline__ void fma2(ull& d, ull a, ull b) {
    asm("fma.rn.f32x2 %0, %1, %2, %0;" : "+l"(d) : "l"(a), "l"(b));
}

__global__ __launch_bounds__(128, 4)
void frfd_conv3x3_kernel(const float* __restrict__ x, float* __restrict__ out) {
    __shared__ __align__(16) float sPatch[2][34 * 34 + 2];   // double buffer
    __shared__ __align__(16) ull   sW[8 * 64 * 9];           // duplicated pairs

    const int tx  = threadIdx.x;       // 0..15 -> column pair
    const int ty  = threadIdx.y;       // 0..7  -> 4-row group
    const int tid = ty * 16 + tx;
    const int bz  = blockIdx.z;
    const int n   = bz >> 3;
    const int cog = bz & 7;

    // stage this block's duplicated weights (36 KB), 16B chunks
    {
        const ulonglong2* src =
            reinterpret_cast<const ulonglong2*>(g_w2 + (size_t)cog * (8 * 64 * 9));
        ulonglong2* dst = reinterpret_cast<ulonglong2*>(sW);
#pragma unroll 3
        for (int i = tid; i < (8 * 64 * 9) / 2; i += 128) dst[i] = src[i];
    }

    const int hb = blockIdx.y * 32;
    const int wb = blockIdx.x * 32;

    // -------- hoisted staging offsets: identical for every ci --------
    int goff[10];
#pragma unroll
    for (int k = 0; k < 10; ++k) {
        int idx = tid + k * 128;
        int pr  = idx / 34;
        int pc  = idx - pr * 34;
        int gh  = hb - 1 + pr;
        int gw2 = wb - 1 + pc;
        bool ok = (idx < 1156) && ((unsigned)gh < 224u) && ((unsigned)gw2 < 224u);
        goff[k] = ok ? gh * 224 + gw2 : -1;
    }

    const float* xn = x + (size_t)n * 64 * 224 * 224;

    // -------- prologue: stage ci = 0 into buffer 0 --------
    float v[10];
    {
        const float* xc = xn;
#pragma unroll
        for (int k = 0; k < 10; ++k)
            v[k] = (goff[k] >= 0) ? xc[goff[k]] : 0.0f;
#pragma unroll
        for (int k = 0; k < 9; ++k) sPatch[0][tid + k * 128] = v[k];
        if (tid < 4) sPatch[0][tid + 1152] = v[9];
    }
    __syncthreads();   // also orders the sW staging

    ull acc[8][4];
#pragma unroll
    for (int co = 0; co < 8; ++co)
#pragma unroll
        for (int rr = 0; rr < 4; ++rr) acc[co][rr] = 0ULL;

    for (int ci = 0; ci < 64; ++ci) {
        const int cur = ci & 1;

        // ---- prefetch ci+1 into registers (overlaps with compute) ----
        if (ci < 63) {
            const float* xc = xn + (size_t)(ci + 1) * (224 * 224);
#pragma unroll
            for (int k = 0; k < 10; ++k)
                v[k] = (goff[k] >= 0) ? xc[goff[k]] : 0.0f;
        }

        // ---- thread window: 6 rows of packed column pairs ----
        ull A[6], B[6], P[6];
#pragma unroll
        for (int r = 0; r < 6; ++r) {
            const float* rowp = &sPatch[cur][(4 * ty + r) * 34 + 2 * tx];
            A[r] = *reinterpret_cast<const ull*>(rowp);
            B[r] = *reinterpret_cast<const ull*>(rowp + 2);
            P[r] = (A[r] >> 32) | (B[r] << 32);
        }

        // ---- 8 co x 4 rows x 9 taps, weights via LDS.64 broadcast ----
        const ull* wci = sW + ci * 9;
#pragma unroll
        for (int co = 0; co < 8; ++co) {
            const ull* wp = wci + co * (64 * 9);
#pragma unroll
            for (int kh = 0; kh < 3; ++kh) {
                ull w0 = wp[kh * 3 + 0];
                ull w1 = wp[kh * 3 + 1];
                ull w2 = wp[kh * 3 + 2];
#pragma unroll
                for (int rr = 0; rr < 4; ++rr) {
                    fma2(acc[co][rr], A[rr + kh], w0);
                    fma2(acc[co][rr], P[rr + kh], w1);
                    fma2(acc[co][rr], B[rr + kh], w2);
                }
            }
        }

        // ---- store prefetched patch into the other buffer ----
        if (ci < 63) {
            float* dstp = sPatch[cur ^ 1];
#pragma unroll
            for (int k = 0; k < 9; ++k) dstp[tid + k * 128] = v[k];
            if (tid < 4) dstp[tid + 1152] = v[9];
        }
        __syncthreads();   // one barrier per ci
    }

    // ---- store: packed pair = contiguous (w, w+1) floats ----
#pragma unroll
    for (int co = 0; co < 8; ++co) {
        size_t cbase = ((size_t)n * 64 + (size_t)cog * 8 + co) * (224 * 224);
#pragma unroll
        for (int rr = 0; rr < 4; ++rr) {
            int h = hb + 4 * ty + rr;
            int w = wb + 2 * tx;
            *reinterpret_cast<ull*>(&out[cbase + (size_t)h * 224 + w]) = acc[co][rr];
        }
    }
}

// --------------------------------- launcher ---------------------------------
extern "C" void kernel_launch(void* const* d_in, const int* in_sizes, int n_in,
                              void* d_out, int out_size) {
    int ix = 0, ispec = 1, ialpha = 2, ipw = 3;
    for (int i = 0; i < n_in; ++i) {
        int s = in_sizes[i];
        if (s == 16 * 64 * 224 * 224) ix = i;
        else if (s == 64 * 64 * 3 * 3) ispec = i;
        else if (s == 1) ialpha = i;
        else if (s == 2) ipw = i;
    }
    const float* x     = (const float*)d_in[ix];
    const float* spec  = (const float*)d_in[ispec];
    const float* alpha = (const float*)d_in[ialpha];
    const float* pw    = (const float*)d_in[ipw];
    float* out = (float*)d_out;

    frfd_wgen_kernel<<<16, 256>>>(spec, alpha, pw);

    dim3 grid(7, 7, 16 * 8);
    dim3 block(16, 8);
    frfd_conv3x3_kernel<<<grid, block>>>(x, out);
}